// round 12
// baseline (speedup 1.0000x reference)
#include <cuda_runtime.h>
#include <cuda_fp16.h>

// Trilinear interpolation: fp16 channel-last scratch + 4-lane gather with a
// 2-stage cp.async (LDGSTS) software pipeline — gather loads live in SMEM,
// not registers, so loads stay in flight during compute (full duty cycle).
//   input  d_in[0]: float32 [16, 128, 128, 128]  (C, z, y, x)
//   coords d_in[1]: float32 [1000000, 3] in [-1, 1]
//   out    d_out  : float32 [16, 1000000]

#define GS        128
#define NCH       16
#define NSPATIAL  (GS * GS * GS)
#define PAD_CELLS (GS * GS + GS + 1)   // +1 plane/row/cell for unclamped +1 corners
#define GATHER_BLOCKS 740              // 148 SMs x 5 CTAs: one persistent wave

// fp16 scratch, zero-initialized (pad region must read as 0.0)
__device__ __align__(128) __half g_trans[(size_t)NCH * (NSPATIAL + PAD_CELLS)];

__device__ __forceinline__ void stg256_evict_last(void* p, unsigned long long a,
                                                  unsigned long long b,
                                                  unsigned long long c,
                                                  unsigned long long d) {
    asm volatile("st.global.L2::evict_last.v4.u64 [%0], {%1,%2,%3,%4};"
                 :: "l"(p), "l"(a), "l"(b), "l"(c), "l"(d) : "memory");
}

__global__ void __launch_bounds__(256) transpose_kernel(const float* __restrict__ in) {
    int idx = blockIdx.x * blockDim.x + threadIdx.x;
    if (idx >= NSPATIAL) return;
    __half2 v[NCH / 2];
#pragma unroll
    for (int c = 0; c < NCH; c += 2) {
        float a = __ldcs(in + (size_t)c * NSPATIAL + idx);        // streaming reads
        float b = __ldcs(in + (size_t)(c + 1) * NSPATIAL + idx);
        v[c / 2] = __floats2half2_rn(a, b);
    }
    const unsigned long long* s = reinterpret_cast<const unsigned long long*>(v);
    stg256_evict_last(g_trans + (size_t)idx * NCH, s[0], s[1], s[2], s[3]);
}

// ---- gather kernel ----

struct W4 { float w0, w1, w2, w3; };

__device__ __forceinline__ void cp16(unsigned smem_addr, const void* gptr) {
    asm volatile("cp.async.cg.shared.global [%0], [%1], 16;"
                 :: "r"(smem_addr), "l"(gptr));
}

// smem layout: [slice 0..3][stage 0..1][tid 0..255][16 B] = 32 KB
//   addr(slice,stage,tid) = sbase + slice*8192 + stage*4096 + tid*16
// -> per instruction (uniform slice/stage) lanes hit consecutive 16 B: no conflicts.
#define SLICE_STRIDE 8192
#define STAGE_STRIDE 4096

// compute weights + issue this point's 4 corner cp.asyncs into the given stage
__device__ __forceinline__ W4 setup_issue(float c0, float c1, float c2,
                                          int lane, unsigned s_addr_stage) {
    // map [-1,1] -> [0,127], clamp in fp; +1 corners may land in the zero pad
    // but always carry weight exactly 0 there.
    float f0 = fminf(fmaxf(fmaf(c0, 63.5f, 63.5f), 0.0f), 127.0f);
    float f1 = fminf(fmaxf(fmaf(c1, 63.5f, 63.5f), 0.0f), 127.0f);
    float f2 = fminf(fmaxf(fmaf(c2, 63.5f, 63.5f), 0.0f), 127.0f);
    float fl0 = floorf(f0), fl1 = floorf(f1), fl2 = floorf(f2);
    float r0 = f0 - fl0, r1 = f1 - fl1, r2 = f2 - fl2;

    int cell00 = (((int)fl0 * GS + (int)fl1) * GS + (int)fl2);
    const char* base = reinterpret_cast<const char*>(g_trans)
                     + (size_t)cell00 * 32 + lane * 16;

    cp16(s_addr_stage + 0 * SLICE_STRIDE, base);
    cp16(s_addr_stage + 1 * SLICE_STRIDE, base + GS * 32);
    cp16(s_addr_stage + 2 * SLICE_STRIDE, base + GS * GS * 32);
    cp16(s_addr_stage + 3 * SLICE_STRIDE, base + GS * GS * 32 + GS * 32);
    asm volatile("cp.async.commit_group;" ::: "memory");

    float wxl = (lane < 2) ? (1.0f - r2) : r2;   // this lane's x-corner weight
    W4 w;
    w.w0 = (1.0f - r0) * (1.0f - r1) * wxl;
    w.w1 = (1.0f - r0) * r1 * wxl;
    w.w2 = r0 * (1.0f - r1) * wxl;
    w.w3 = r0 * r1 * wxl;
    return w;
}

__global__ void __launch_bounds__(256, 5) gather_kernel(const float* __restrict__ coords,
                                                        float* __restrict__ out,
                                                        int N) {
    __shared__ __align__(16) char s_buf[4 * 2 * 256 * 16];   // 32 KB

    int tid  = threadIdx.x;
    int t    = blockIdx.x * 256 + tid;
    int lane = t & 3;          // 0: x0/ch0-7  1: x0/ch8-15  2: x1/ch0-7  3: x1/ch8-15
    int n    = t >> 2;
    int stride = (gridDim.x * 256) >> 2;
    if (n >= N) return;

    unsigned sbase = (unsigned)__cvta_generic_to_shared(s_buf) + tid * 16;

    // store-slice constants: lane0 ch0-3, lane2 ch4-7, lane1 ch8-11, lane3 ch12-15
    int sel    = lane >> 1;
    int chbase = (lane & 1) * 8 + sel * 4;

    // ---- prologue: point A into stage 0 ----
    float a0 = __ldg(coords + 3 * n + 0);
    float a1 = __ldg(coords + 3 * n + 1);
    float a2 = __ldg(coords + 3 * n + 2);
    W4 wA = setup_issue(a0, a1, a2, lane, sbase);

    int  nB   = n + stride;
    bool hasB = (nB < N);
    int  nBc  = hasB ? nB : n;
    float b0 = __ldg(coords + 3 * nBc + 0);
    float b1 = __ldg(coords + 3 * nBc + 1);
    float b2 = __ldg(coords + 3 * nBc + 2);

    unsigned st = 0;   // stage holding point A

    while (true) {
        // issue point B into the other stage (keeps loads in flight during compute)
        W4 wB;
        if (hasB) wB = setup_issue(b0, b1, b2, lane, sbase + (st ^ 1) * STAGE_STRIDE);

        // prefetch coords for point C
        int  nC   = nB + stride;
        bool hasC = hasB && (nC < N);
        int  nCc  = hasC ? nC : n;
        float e0 = __ldg(coords + 3 * nCc + 0);
        float e1 = __ldg(coords + 3 * nCc + 1);
        float e2 = __ldg(coords + 3 * nCc + 2);

        // wait for point A's group (oldest)
        if (hasB) asm volatile("cp.async.wait_group 1;" ::: "memory");
        else      asm volatile("cp.async.wait_group 0;" ::: "memory");

        // consume point A from smem
        float acc[8];
#pragma unroll
        for (int k = 0; k < 8; k++) acc[k] = 0.0f;
        {
            const char* sp = s_buf + (size_t)tid * 16 + st * STAGE_STRIDE;
            float wv[4] = {wA.w0, wA.w1, wA.w2, wA.w3};
#pragma unroll
            for (int s = 0; s < 4; s++) {
                uint4 raw = *reinterpret_cast<const uint4*>(sp + s * SLICE_STRIDE);
                const unsigned* r = reinterpret_cast<const unsigned*>(&raw);
                float w = wv[s];
#pragma unroll
                for (int j = 0; j < 4; j++) {
                    float2 v = __half22float2(*reinterpret_cast<const __half2*>(&r[j]));
                    acc[2 * j + 0] = fmaf(w, v.x, acc[2 * j + 0]);
                    acc[2 * j + 1] = fmaf(w, v.y, acc[2 * j + 1]);
                }
            }
        }

        // combine x0/x1 partials: partner lane = lane^2 (same point, always active)
        unsigned mask = __activemask();
#pragma unroll
        for (int k = 0; k < 8; k++) {
            acc[k] += __shfl_xor_sync(mask, acc[k], 2);
        }

        size_t nn = (size_t)n;
#pragma unroll
        for (int j = 0; j < 4; j++) {
            __stcs(out + (size_t)(chbase + j) * N + nn, acc[sel * 4 + j]);
        }

        if (!hasB) break;
        // rotate pipeline
        n = nB; wA = wB;
        nB = nC; hasB = hasC;
        b0 = e0; b1 = e1; b2 = e2;
        st ^= 1;
    }
}

extern "C" void kernel_launch(void* const* d_in, const int* in_sizes, int n_in,
                              void* d_out, int out_size) {
    const float* input  = (const float*)d_in[0];
    const float* coords = (const float*)d_in[1];
    float* out = (float*)d_out;
    int N = in_sizes[1] / 3;

    transpose_kernel<<<(NSPATIAL + 255) / 256, 256>>>(input);

    long long threads = 4LL * N;
    int maxblocks = (int)((threads + 255) / 256);
    int blocks = GATHER_BLOCKS < maxblocks ? GATHER_BLOCKS : maxblocks;
    gather_kernel<<<blocks, 256>>>(coords, out, N);
}

// round 13
// speedup vs baseline: 1.2797x; 1.2797x over previous
#include <cuda_runtime.h>
#include <cuda_fp16.h>

// Trilinear interpolation: fp16 channel-last scratch + 4-lane pair gather.
// R5 structure (best measured) with ld.global.cg grid loads (L1 bypass,
// sector-granular L2 fills, no L1 line allocation) — tests whether the
// 42us gather plateau is L1-allocation overhead or raw return bandwidth.
//   input  d_in[0]: float32 [16, 128, 128, 128]  (C, z, y, x)
//   coords d_in[1]: float32 [1000000, 3] in [-1, 1]
//   out    d_out  : float32 [16, 1000000]

#define GS        128
#define NCH       16
#define NSPATIAL  (GS * GS * GS)
#define PAD_CELLS (GS * GS + GS + 1)   // +1 plane/row/cell for unclamped +1 corners

// fp16 scratch, zero-initialized (pad region must read as 0.0)
__device__ __align__(128) __half g_trans[(size_t)NCH * (NSPATIAL + PAD_CELLS)];

__device__ __forceinline__ unsigned long long make_evict_last_policy() {
    unsigned long long pol;
    asm volatile("createpolicy.fractional.L2::evict_last.b64 %0, 1.0;" : "=l"(pol));
    return pol;
}

// L1-bypassing gather load: .cg (cache at L2 only) + evict_last L2 hint
__device__ __forceinline__ uint4 ldg_cg_hint(const void* p, unsigned long long pol) {
    uint4 v;
    asm volatile("ld.global.cg.L2::cache_hint.v4.u32 {%0,%1,%2,%3}, [%4], %5;"
                 : "=r"(v.x), "=r"(v.y), "=r"(v.z), "=r"(v.w)
                 : "l"(p), "l"(pol));
    return v;
}

__device__ __forceinline__ void stg256_evict_last(void* p, unsigned long long a,
                                                  unsigned long long b,
                                                  unsigned long long c,
                                                  unsigned long long d) {
    asm volatile("st.global.L2::evict_last.v4.u64 [%0], {%1,%2,%3,%4};"
                 :: "l"(p), "l"(a), "l"(b), "l"(c), "l"(d) : "memory");
}

__global__ void __launch_bounds__(256) transpose_kernel(const float* __restrict__ in) {
    int idx = blockIdx.x * blockDim.x + threadIdx.x;
    if (idx >= NSPATIAL) return;
    __half2 v[NCH / 2];
#pragma unroll
    for (int c = 0; c < NCH; c += 2) {
        float a = __ldcs(in + (size_t)c * NSPATIAL + idx);        // streaming reads
        float b = __ldcs(in + (size_t)(c + 1) * NSPATIAL + idx);
        v[c / 2] = __floats2half2_rn(a, b);
    }
    const unsigned long long* s = reinterpret_cast<const unsigned long long*>(v);
    // grid born L2-resident with retention priority (single 32B store)
    stg256_evict_last(g_trans + (size_t)idx * NCH, s[0], s[1], s[2], s[3]);
}

__global__ void __launch_bounds__(256, 8) gather_kernel(const float* __restrict__ coords,
                                                        float* __restrict__ out,
                                                        int N) {
    int t    = blockIdx.x * blockDim.x + threadIdx.x;
    int n    = t >> 2;        // point index
    int lane = t & 3;         // 0: x0/ch0-7  1: x0/ch8-15  2: x1/ch0-7  3: x1/ch8-15
    if (n >= N) return;

    unsigned long long pol = make_evict_last_policy();

    float c0 = __ldcs(coords + 3 * n + 0);
    float c1 = __ldcs(coords + 3 * n + 1);
    float c2 = __ldcs(coords + 3 * n + 2);
    // map [-1,1] -> [0,127], clamp in fp (indices then always in range;
    // the +1 corner may overflow into the zero pad but carries weight 0)
    float f0 = fminf(fmaxf(fmaf(c0, 63.5f, 63.5f), 0.0f), 127.0f);
    float f1 = fminf(fmaxf(fmaf(c1, 63.5f, 63.5f), 0.0f), 127.0f);
    float f2 = fminf(fmaxf(fmaf(c2, 63.5f, 63.5f), 0.0f), 127.0f);

    float fl0 = floorf(f0), fl1 = floorf(f1), fl2 = floorf(f2);
    float r0 = f0 - fl0, r1 = f1 - fl1, r2 = f2 - fl2;

    int iz = (int)fl0, iy = (int)fl1, ix = (int)fl2;
    int cell00 = (iz * GS + iy) * GS + ix;

    float wz[2] = {1.0f - r0, r0};
    float wy[2] = {1.0f - r1, r1};
    float wxl   = (lane < 2) ? (1.0f - r2) : r2;   // this lane's x-corner weight

    const char* base = reinterpret_cast<const char*>(g_trans)
                     + (size_t)cell00 * 32 + lane * 16;

    float acc[8];
#pragma unroll
    for (int k = 0; k < 8; k++) acc[k] = 0.0f;

#pragma unroll
    for (int a = 0; a < 2; a++) {
#pragma unroll
        for (int b = 0; b < 2; b++) {
            float w = wz[a] * wy[b] * wxl;
            uint4 raw = ldg_cg_hint(
                base + ((size_t)a * (GS * GS) + (size_t)b * GS) * 32, pol);
            float2 v0 = __half22float2(*reinterpret_cast<__half2*>(&raw.x));
            float2 v1 = __half22float2(*reinterpret_cast<__half2*>(&raw.y));
            float2 v2 = __half22float2(*reinterpret_cast<__half2*>(&raw.z));
            float2 v3 = __half22float2(*reinterpret_cast<__half2*>(&raw.w));
            acc[0] = fmaf(w, v0.x, acc[0]);
            acc[1] = fmaf(w, v0.y, acc[1]);
            acc[2] = fmaf(w, v1.x, acc[2]);
            acc[3] = fmaf(w, v1.y, acc[3]);
            acc[4] = fmaf(w, v2.x, acc[4]);
            acc[5] = fmaf(w, v2.y, acc[5]);
            acc[6] = fmaf(w, v3.x, acc[6]);
            acc[7] = fmaf(w, v3.y, acc[7]);
        }
    }

    // combine x0/x1 partials: partner lane is lane^2 (same point, guaranteed active)
    unsigned mask = __activemask();
#pragma unroll
    for (int k = 0; k < 8; k++) {
        acc[k] += __shfl_xor_sync(mask, acc[k], 2);
    }

    // lanes 0,2 hold final ch0-7; lanes 1,3 hold final ch8-15.
    //   lane0: ch0-3  lane2: ch4-7  lane1: ch8-11  lane3: ch12-15
    int sel    = lane >> 1;
    int chbase = (lane & 1) * 8 + sel * 4;
    size_t nn  = (size_t)n;
#pragma unroll
    for (int j = 0; j < 4; j++) {
        __stcs(out + (size_t)(chbase + j) * N + nn, acc[sel * 4 + j]);
    }
}

extern "C" void kernel_launch(void* const* d_in, const int* in_sizes, int n_in,
                              void* d_out, int out_size) {
    const float* input  = (const float*)d_in[0];
    const float* coords = (const float*)d_in[1];
    float* out = (float*)d_out;
    int N = in_sizes[1] / 3;

    transpose_kernel<<<(NSPATIAL + 255) / 256, 256>>>(input);

    long long threads = 4LL * N;
    int blocks = (int)((threads + 255) / 256);
    gather_kernel<<<blocks, 256>>>(coords, out, N);
}

// round 14
// speedup vs baseline: 1.2872x; 1.0059x over previous
#include <cuda_runtime.h>
#include <cuda_fp16.h>

// Trilinear interpolation: fp16 channel-last scratch + 4-lane pair gather.
// R5 gather structure (best measured) + single-LDG warp-cooperative coords
// load (1 L1 wavefront instead of 3) distributed via shuffles.
//   input  d_in[0]: float32 [16, 128, 128, 128]  (C, z, y, x)
//   coords d_in[1]: float32 [1000000, 3] in [-1, 1]
//   out    d_out  : float32 [16, 1000000]

#define GS        128
#define NCH       16
#define NSPATIAL  (GS * GS * GS)
#define PAD_CELLS (GS * GS + GS + 1)   // +1 plane/row/cell for unclamped +1 corners

// fp16 scratch, zero-initialized (pad region must read as 0.0)
__device__ __align__(128) __half g_trans[(size_t)NCH * (NSPATIAL + PAD_CELLS)];

__device__ __forceinline__ unsigned long long make_evict_last_policy() {
    unsigned long long pol;
    asm volatile("createpolicy.fractional.L2::evict_last.b64 %0, 1.0;" : "=l"(pol));
    return pol;
}

__device__ __forceinline__ uint4 ldg_hint(const void* p, unsigned long long pol) {
    uint4 v;
    asm volatile("ld.global.L2::cache_hint.v4.u32 {%0,%1,%2,%3}, [%4], %5;"
                 : "=r"(v.x), "=r"(v.y), "=r"(v.z), "=r"(v.w)
                 : "l"(p), "l"(pol));
    return v;
}

__device__ __forceinline__ void stg256_evict_last(void* p, unsigned long long a,
                                                  unsigned long long b,
                                                  unsigned long long c,
                                                  unsigned long long d) {
    asm volatile("st.global.L2::evict_last.v4.u64 [%0], {%1,%2,%3,%4};"
                 :: "l"(p), "l"(a), "l"(b), "l"(c), "l"(d) : "memory");
}

__global__ void __launch_bounds__(256) transpose_kernel(const float* __restrict__ in) {
    int idx = blockIdx.x * blockDim.x + threadIdx.x;
    if (idx >= NSPATIAL) return;
    __half2 v[NCH / 2];
#pragma unroll
    for (int c = 0; c < NCH; c += 2) {
        float a = __ldcs(in + (size_t)c * NSPATIAL + idx);        // streaming reads
        float b = __ldcs(in + (size_t)(c + 1) * NSPATIAL + idx);
        v[c / 2] = __floats2half2_rn(a, b);
    }
    const unsigned long long* s = reinterpret_cast<const unsigned long long*>(v);
    // grid born L2-resident with retention priority (single 32B store)
    stg256_evict_last(g_trans + (size_t)idx * NCH, s[0], s[1], s[2], s[3]);
}

__global__ void __launch_bounds__(256, 8) gather_kernel(const float* __restrict__ coords,
                                                        float* __restrict__ out,
                                                        int N) {
    int t    = blockIdx.x * blockDim.x + threadIdx.x;
    int n    = t >> 2;        // point index
    int lane = t & 3;         // 0: x0/ch0-7  1: x0/ch8-15  2: x1/ch0-7  3: x1/ch8-15
    if (n >= N) return;

    unsigned long long pol = make_evict_last_policy();
    unsigned mask = __activemask();   // active lanes form a prefix of the warp

    // ---- warp-cooperative coords load: one LDG (96 B = 1 line) + 3 shuffles ----
    // warp covers 8 consecutive points = 24 floats; lane L (L<24) loads float L.
    int wlane = threadIdx.x & 31;
    int pbase = n - (wlane >> 2);             // warp's first point
    float cv = 0.0f;
    if (wlane < 24) {
        long long idx = (long long)pbase * 3 + wlane;
        long long maxi = (long long)N * 3 - 1;
        cv = __ldcs(coords + (idx < maxi ? idx : maxi));
    }
    int g  = wlane >> 2;                      // this lane's point-group within warp
    float c0 = __shfl_sync(mask, cv, 3 * g + 0);
    float c1 = __shfl_sync(mask, cv, 3 * g + 1);
    float c2 = __shfl_sync(mask, cv, 3 * g + 2);

    // map [-1,1] -> [0,127], clamp in fp (indices then always in range;
    // the +1 corner may overflow into the zero pad but carries weight 0)
    float f0 = fminf(fmaxf(fmaf(c0, 63.5f, 63.5f), 0.0f), 127.0f);
    float f1 = fminf(fmaxf(fmaf(c1, 63.5f, 63.5f), 0.0f), 127.0f);
    float f2 = fminf(fmaxf(fmaf(c2, 63.5f, 63.5f), 0.0f), 127.0f);

    float fl0 = floorf(f0), fl1 = floorf(f1), fl2 = floorf(f2);
    float r0 = f0 - fl0, r1 = f1 - fl1, r2 = f2 - fl2;

    int cell00 = (((int)fl0 * GS + (int)fl1) * GS + (int)fl2);

    float wz[2] = {1.0f - r0, r0};
    float wy[2] = {1.0f - r1, r1};
    float wxl   = (lane < 2) ? (1.0f - r2) : r2;   // this lane's x-corner weight

    const char* base = reinterpret_cast<const char*>(g_trans)
                     + (size_t)cell00 * 32 + lane * 16;

    float acc[8];
#pragma unroll
    for (int k = 0; k < 8; k++) acc[k] = 0.0f;

#pragma unroll
    for (int a = 0; a < 2; a++) {
#pragma unroll
        for (int b = 0; b < 2; b++) {
            float w = wz[a] * wy[b] * wxl;
            uint4 raw = ldg_hint(
                base + ((size_t)a * (GS * GS) + (size_t)b * GS) * 32, pol);
            float2 v0 = __half22float2(*reinterpret_cast<__half2*>(&raw.x));
            float2 v1 = __half22float2(*reinterpret_cast<__half2*>(&raw.y));
            float2 v2 = __half22float2(*reinterpret_cast<__half2*>(&raw.z));
            float2 v3 = __half22float2(*reinterpret_cast<__half2*>(&raw.w));
            acc[0] = fmaf(w, v0.x, acc[0]);
            acc[1] = fmaf(w, v0.y, acc[1]);
            acc[2] = fmaf(w, v1.x, acc[2]);
            acc[3] = fmaf(w, v1.y, acc[3]);
            acc[4] = fmaf(w, v2.x, acc[4]);
            acc[5] = fmaf(w, v2.y, acc[5]);
            acc[6] = fmaf(w, v3.x, acc[6]);
            acc[7] = fmaf(w, v3.y, acc[7]);
        }
    }

    // combine x0/x1 partials: partner lane is lane^2 (same point, guaranteed active)
#pragma unroll
    for (int k = 0; k < 8; k++) {
        acc[k] += __shfl_xor_sync(mask, acc[k], 2);
    }

    // lanes 0,2 hold final ch0-7; lanes 1,3 hold final ch8-15.
    //   lane0: ch0-3  lane2: ch4-7  lane1: ch8-11  lane3: ch12-15
    int sel    = lane >> 1;
    int chbase = (lane & 1) * 8 + sel * 4;
    size_t nn  = (size_t)n;
#pragma unroll
    for (int j = 0; j < 4; j++) {
        __stcs(out + (size_t)(chbase + j) * N + nn, acc[sel * 4 + j]);
    }
}

extern "C" void kernel_launch(void* const* d_in, const int* in_sizes, int n_in,
                              void* d_out, int out_size) {
    const float* input  = (const float*)d_in[0];
    const float* coords = (const float*)d_in[1];
    float* out = (float*)d_out;
    int N = in_sizes[1] / 3;

    transpose_kernel<<<(NSPATIAL + 255) / 256, 256>>>(input);

    long long threads = 4LL * N;
    int blocks = (int)((threads + 255) / 256);
    gather_kernel<<<blocks, 256>>>(coords, out, N);
}